// round 1
// baseline (speedup 1.0000x reference)
#include <cuda_runtime.h>

// Problem constants
#define B_   16
#define CIN  8
#define COUT 32
#define DIN  48   // input D=H=W
#define DOUT 46   // output D=H=W (valid conv, k=3)
#define KVOL 216  // 8*3*3*3
#define HT   4    // output H rows per block
#define TH   (HT + 2)   // input H rows per tile
#define TPB  192  // 4 rows x 48 lanes

#define NPOS_F   (46.f * 46.f * 46.f)          // 97336 spatial positions
#define EPSGN    1e-5f

// Scratch: per-(b) channel sums [b][0:32]=sum(v), [b][32:64]=sum(v^2); transposed weights
__device__ float g_sums[B_ * 64];
__device__ float g_wT[KVOL * COUT];   // [k][oc]

// ---------------------------------------------------------------------------
// Prep: zero accumulators + transpose weights to [k][oc] layout
// ---------------------------------------------------------------------------
__global__ void prep_kernel(const float* __restrict__ w)
{
    int t = threadIdx.x;
    if (t < B_ * 64) g_sums[t] = 0.f;
    for (int i = t; i < KVOL * COUT; i += 1024) {
        int k = i >> 5, oc = i & 31;
        g_wT[i] = w[oc * KVOL + k];
    }
}

// ---------------------------------------------------------------------------
// Fused conv3d + bias + hardswish + per-channel sum / sum-of-squares
// grid = (12 h-chunks, 46 d, 16 b), block = 192
// ---------------------------------------------------------------------------
extern __shared__ float smem[];

__global__ void __launch_bounds__(TPB)
conv_fused_kernel(const float* __restrict__ x,
                  const float* __restrict__ bias)
{
    float* x_s = smem;                              // [8][3][TH][48]
    float* w_s = smem + CIN * 3 * TH * DIN;         // [216][32]
    float* b_s = w_s + KVOL * COUT;                 // [32]

    const int b  = blockIdx.z;
    const int d0 = blockIdx.y;          // output d -> input d0..d0+2
    const int h0 = blockIdx.x * HT;     // output rows h0..h0+HT-1
    const int tid = threadIdx.x;

    // --- load transposed weights (coalesced read, conflict-free store) ---
    for (int i = tid; i < KVOL * COUT; i += TPB) w_s[i] = g_wT[i];
    if (tid < COUT) b_s[tid] = bias[tid];

    // --- load input tile: 8 ch x 3 d x TH rows x 48 w ---
    for (int i = tid; i < CIN * 3 * TH * DIN; i += TPB) {
        int wq = i % DIN;
        int r  = i / DIN;
        int hh = r % TH;  r /= TH;
        int dz = r % 3;
        int ic = r / 3;
        int hg = h0 + hh;
        float v = 0.f;
        if (hg < DIN)
            v = x[(((b * CIN + ic) * DIN + (d0 + dz)) * DIN + hg) * DIN + wq];
        x_s[i] = v;
    }
    __syncthreads();

    // --- compute one output position (hl, wq) for all 32 channels ---
    const int wq = tid % DIN;        // 0..47 (valid < 46)
    const int hl = tid / DIN;        // 0..3
    const bool valid = (wq < DOUT) && (h0 + hl < DOUT);
    const int wc = min(wq, DOUT - 1);   // clamp so smem reads stay in-bounds

    float acc[COUT];
    #pragma unroll
    for (int i = 0; i < COUT; i++) acc[i] = 0.f;

    #pragma unroll 1
    for (int ic = 0; ic < CIN; ic++) {
        #pragma unroll 1
        for (int kd = 0; kd < 3; kd++) {
            const float* xbase = &x_s[((ic * 3 + kd) * TH) * DIN];
            const float* wbase = &w_s[((ic * 3 + kd) * 9) * COUT];
            #pragma unroll
            for (int kh = 0; kh < 3; kh++) {
                const float* xr = &xbase[(hl + kh) * DIN + wc];
                float x0 = xr[0], x1 = xr[1], x2 = xr[2];
                const float4* w0 = (const float4*)&wbase[(kh * 3 + 0) * COUT];
                const float4* w1 = (const float4*)&wbase[(kh * 3 + 1) * COUT];
                const float4* w2 = (const float4*)&wbase[(kh * 3 + 2) * COUT];
                #pragma unroll
                for (int j = 0; j < 8; j++) {
                    float4 a = w0[j], bb = w1[j], cc = w2[j];
                    acc[4*j+0] += a.x * x0 + bb.x * x1 + cc.x * x2;
                    acc[4*j+1] += a.y * x0 + bb.y * x1 + cc.y * x2;
                    acc[4*j+2] += a.z * x0 + bb.z * x1 + cc.z * x2;
                    acc[4*j+3] += a.w * x0 + bb.w * x1 + cc.w * x2;
                }
            }
        }
    }

    // --- bias + hardswish + warp reduce + global accumulate ---
    float* outp = &g_sums[b * 64];
    #pragma unroll
    for (int oc = 0; oc < COUT; oc++) {
        float y = acc[oc] + b_s[oc];
        float t = fminf(fmaxf(y + 3.f, 0.f), 6.f);
        float v = valid ? (y * t * (1.f / 6.f)) : 0.f;
        float v2 = v * v;
        #pragma unroll
        for (int off = 16; off; off >>= 1) {
            v  += __shfl_xor_sync(0xffffffffu, v,  off);
            v2 += __shfl_xor_sync(0xffffffffu, v2, off);
        }
        if ((tid & 31) == 0) {
            atomicAdd(&outp[oc],      v);
            atomicAdd(&outp[32 + oc], v2);
        }
    }
}

// ---------------------------------------------------------------------------
// Finalize: GroupNorm stats from channel sums, emit [B, C] means
// out[b,c] = (mean_c - mean_g) * rsqrt(var_g + eps) * gamma[c] + beta[c]
// ---------------------------------------------------------------------------
__global__ void finalize_kernel(const float* __restrict__ gn_w,
                                const float* __restrict__ gn_b,
                                float* __restrict__ out)
{
    int i = threadIdx.x;
    if (i >= B_ * COUT) return;
    int b = i >> 5, c = i & 31;
    int g = c >> 3;              // 4 groups of 8 channels
    const float* s = &g_sums[b * 64];
    float S1 = 0.f, S2 = 0.f;
    #pragma unroll
    for (int j = 0; j < 8; j++) {
        S1 += s[g * 8 + j];
        S2 += s[32 + g * 8 + j];
    }
    float invNg = 1.f / (8.f * NPOS_F);
    float mean  = S1 * invNg;
    float var   = S2 * invNg - mean * mean;
    float rinv  = rsqrtf(var + EPSGN);
    float mc    = s[c] * (1.f / NPOS_F);
    out[i] = (mc - mean) * rinv * gn_w[c] + gn_b[c];
}

// ---------------------------------------------------------------------------
extern "C" void kernel_launch(void* const* d_in, const int* in_sizes, int n_in,
                              void* d_out, int out_size)
{
    const float* x      = (const float*)d_in[0];
    const float* weight = (const float*)d_in[1];
    const float* bias   = (const float*)d_in[2];
    const float* gn_w   = (const float*)d_in[3];
    const float* gn_b   = (const float*)d_in[4];
    float* out = (float*)d_out;

    const int smem_bytes = (CIN * 3 * TH * DIN + KVOL * COUT + COUT) * (int)sizeof(float);
    cudaFuncSetAttribute(conv_fused_kernel,
                         cudaFuncAttributeMaxDynamicSharedMemorySize, smem_bytes);

    prep_kernel<<<1, 1024>>>(weight);

    dim3 grid((DOUT + HT - 1) / HT, DOUT, B_);   // (12, 46, 16)
    conv_fused_kernel<<<grid, TPB, smem_bytes>>>(x, bias);

    finalize_kernel<<<1, 512>>>(gn_w, gn_b, out);
}

// round 2
// speedup vs baseline: 2.6213x; 2.6213x over previous
#include <cuda_runtime.h>

// Problem constants
#define B_   16
#define CIN  8
#define COUT 32
#define DIN  48   // input D=H=W
#define DOUT 46   // output D=H=W (valid conv, k=3)
#define KVOL 216  // 8*3*3*3
#define HT   8    // output H rows per block (2 per thread)
#define TH   (HT + 2)   // input H rows per tile
#define TPB  192  // 4 row-pairs x 48 lanes

#define NPOS_F   (46.f * 46.f * 46.f)
#define EPSGN    1e-5f

typedef unsigned long long u64;

__device__ float g_sums[B_ * 64];
__device__ float g_wT[KVOL * COUT];   // [k][oc]

// ---- packed fp32 helpers (fma.rn.f32x2 — FFMA2, ptxas never emits this) ----
__device__ __forceinline__ void ffma2(u64 &d, u64 a, u64 b) {
    asm("fma.rn.f32x2 %0, %1, %2, %0;" : "+l"(d) : "l"(a), "l"(b));
}
__device__ __forceinline__ u64 dup2(float x) {
    u64 r; asm("mov.b64 %0, {%1, %1};" : "=l"(r) : "f"(x)); return r;
}
__device__ __forceinline__ float2 unpack2(u64 v) {
    float2 f; asm("mov.b64 {%0, %1}, %2;" : "=f"(f.x), "=f"(f.y) : "l"(v)); return f;
}

// ---------------------------------------------------------------------------
// Prep: zero accumulators + transpose weights to [k][oc]
// ---------------------------------------------------------------------------
__global__ void prep_kernel(const float* __restrict__ w)
{
    int t = threadIdx.x;
    if (t < B_ * 64) g_sums[t] = 0.f;
    for (int i = t; i < KVOL * COUT; i += 1024) {
        int k = i >> 5, oc = i & 31;
        g_wT[i] = w[oc * KVOL + k];
    }
}

// ---------------------------------------------------------------------------
// Fused conv3d + bias + hardswish + per-channel sum / sum-sq
// grid = (6 h-chunks, 46 d, 16 b), block = 192
// Each thread: 2 adjacent h rows x 1 w x 32 channels (16 f32x2 pairs each)
// ---------------------------------------------------------------------------
extern __shared__ float smem[];

__global__ void __launch_bounds__(TPB)
conv_fused_kernel(const float* __restrict__ x,
                  const float* __restrict__ bias)
{
    float* x_s  = smem;                              // [8][3][TH][48]
    float* w_s  = smem + CIN * 3 * TH * DIN;         // [216][32]
    float* s_red = w_s + KVOL * COUT;                // [64]
    float* b_s  = s_red + 64;                        // [32]

    const int b  = blockIdx.z;
    const int d0 = blockIdx.y;
    const int h0 = blockIdx.x * HT;
    const int tid = threadIdx.x;

    for (int i = tid; i < KVOL * COUT; i += TPB) w_s[i] = g_wT[i];
    if (tid < 64) s_red[tid] = 0.f;
    if (tid < COUT) b_s[tid] = bias[tid];

    for (int i = tid; i < CIN * 3 * TH * DIN; i += TPB) {
        int wq = i % DIN;
        int r  = i / DIN;
        int hh = r % TH;  r /= TH;
        int dz = r % 3;
        int ic = r / 3;
        int hg = h0 + hh;
        float v = 0.f;
        if (hg < DIN)
            v = x[(((b * CIN + ic) * DIN + (d0 + dz)) * DIN + hg) * DIN + wq];
        x_s[i] = v;
    }
    __syncthreads();

    const int wq = tid % DIN;        // 0..47
    const int hp = tid / DIN;        // 0..3 -> local rows 2hp, 2hp+1
    const bool vw = (wq < DOUT);
    const bool vA = vw && (h0 + 2 * hp     < DOUT);
    const bool vB = vw && (h0 + 2 * hp + 1 < DOUT);
    const int wc = min(wq, DOUT - 1);    // clamp: smem reads stay in-bounds

    u64 accA[16], accB[16];
    #pragma unroll
    for (int p = 0; p < 16; p++) { accA[p] = 0ull; accB[p] = 0ull; }

    #pragma unroll 1
    for (int ic = 0; ic < CIN; ic++) {
        #pragma unroll 1
        for (int kd = 0; kd < 3; kd++) {
            const float* xb = &x_s[((ic * 3 + kd) * TH + 2 * hp) * DIN + wc];
            const float* wb = &w_s[(ic * 3 + kd) * 9 * COUT];

            // 4 rows x 3 taps of x, duplicated into f32x2 pairs
            u64 dx[4][3];
            #pragma unroll
            for (int r = 0; r < 4; r++)
                #pragma unroll
                for (int t = 0; t < 3; t++)
                    dx[r][t] = dup2(xb[r * DIN + t]);

            #pragma unroll
            for (int kh = 0; kh < 3; kh++) {
                #pragma unroll
                for (int t = 0; t < 3; t++) {
                    u64 xa = dx[kh][t];
                    u64 xv = dx[kh + 1][t];
                    const ulonglong2* wp =
                        (const ulonglong2*)&wb[(kh * 3 + t) * COUT];
                    #pragma unroll
                    for (int j = 0; j < 8; j++) {
                        ulonglong2 W = wp[j];          // LDS.128 broadcast
                        ffma2(accA[2 * j],     W.x, xa);
                        ffma2(accA[2 * j + 1], W.y, xa);
                        ffma2(accB[2 * j],     W.x, xv);
                        ffma2(accB[2 * j + 1], W.y, xv);
                    }
                }
            }
        }
    }

    // --- bias + hardswish + warp reduce + block reduce ---
    const unsigned lane = tid & 31;
    #pragma unroll
    for (int p = 0; p < 16; p++) {
        float2 a = unpack2(accA[p]);
        float2 c2 = unpack2(accB[p]);
        #pragma unroll
        for (int q = 0; q < 2; q++) {
            int c = 2 * p + q;
            float ya = (q ? a.y : a.x) + b_s[c];
            float yb = (q ? c2.y : c2.x) + b_s[c];
            float ta = fminf(fmaxf(ya + 3.f, 0.f), 6.f);
            float tb = fminf(fmaxf(yb + 3.f, 0.f), 6.f);
            float va = vA ? ya * ta * (1.f / 6.f) : 0.f;
            float vb = vB ? yb * tb * (1.f / 6.f) : 0.f;
            float v  = va + vb;
            float v2 = va * va + vb * vb;
            #pragma unroll
            for (int off = 16; off; off >>= 1) {
                v  += __shfl_xor_sync(0xffffffffu, v,  off);
                v2 += __shfl_xor_sync(0xffffffffu, v2, off);
            }
            if (lane == 0) {
                atomicAdd(&s_red[c],      v);
                atomicAdd(&s_red[32 + c], v2);
            }
        }
    }
    __syncthreads();
    if (tid < 64) atomicAdd(&g_sums[b * 64 + tid], s_red[tid]);
}

// ---------------------------------------------------------------------------
// Finalize: GroupNorm stats from channel sums -> [B, C]
// ---------------------------------------------------------------------------
__global__ void finalize_kernel(const float* __restrict__ gn_w,
                                const float* __restrict__ gn_b,
                                float* __restrict__ out)
{
    int i = threadIdx.x;
    if (i >= B_ * COUT) return;
    int b = i >> 5, c = i & 31;
    int g = c >> 3;
    const float* s = &g_sums[b * 64];
    float S1 = 0.f, S2 = 0.f;
    #pragma unroll
    for (int j = 0; j < 8; j++) {
        S1 += s[g * 8 + j];
        S2 += s[32 + g * 8 + j];
    }
    float invNg = 1.f / (8.f * NPOS_F);
    float mean  = S1 * invNg;
    float var   = S2 * invNg - mean * mean;
    float rinv  = rsqrtf(var + EPSGN);
    float mc    = s[c] * (1.f / NPOS_F);
    out[i] = (mc - mean) * rinv * gn_w[c] + gn_b[c];
}

// ---------------------------------------------------------------------------
extern "C" void kernel_launch(void* const* d_in, const int* in_sizes, int n_in,
                              void* d_out, int out_size)
{
    const float* x      = (const float*)d_in[0];
    const float* weight = (const float*)d_in[1];
    const float* bias   = (const float*)d_in[2];
    const float* gn_w   = (const float*)d_in[3];
    const float* gn_b   = (const float*)d_in[4];
    float* out = (float*)d_out;

    const int smem_bytes =
        (CIN * 3 * TH * DIN + KVOL * COUT + 64 + COUT) * (int)sizeof(float);
    cudaFuncSetAttribute(conv_fused_kernel,
                         cudaFuncAttributeMaxDynamicSharedMemorySize, smem_bytes);

    prep_kernel<<<1, 1024>>>(weight);

    dim3 grid((DOUT + HT - 1) / HT, DOUT, B_);   // (6, 46, 16)
    conv_fused_kernel<<<grid, TPB, smem_bytes>>>(x, bias);

    finalize_kernel<<<1, 512>>>(gn_w, gn_b, out);
}